// round 2
// baseline (speedup 1.0000x reference)
#include <cuda_runtime.h>
#include <math_constants.h>

#define NB 2
#define NQ 2048
#define NK 2048
#define DMODEL 512
#define NH 8
#define DHEAD 64
#define NF 5
#define LOG2E 1.44269504088896f

// Scratch (allocation-free rule: __device__ globals)
__device__ float g_q[NB*NH*NQ*DHEAD];     // [b][h][q][dh]
__device__ float g_k[NB*NH*NK*DHEAD];     // [b][h][k][dh]
__device__ float g_v[NB*NH*NK*DHEAD];     // [b][h][k][dh]
__device__ float g_ctx[NB*NQ*DMODEL];     // [b][q][h*64+dh]

__device__ __forceinline__ float ex2f(float x) {
    float y; asm("ex2.approx.ftz.f32 %0, %1;" : "=f"(y) : "f"(x)); return y;
}
__device__ __forceinline__ float rsqrtaf(float x) {
    float y; asm("rsqrt.approx.ftz.f32 %0, %1;" : "=f"(y) : "f"(x)); return y;
}

// ---------------------------------------------------------------------------
// GEMM: out = (X[M,512] @ W[512,512] + bias) * scale
// split==1: write head-split layout out[((batch*NH+h)*2048 + s)*64 + dh]
// split==0: write out[row*512 + n]
// M = 4096 fixed. Tiles 64x64x16, 256 threads, 4x4 per thread.
// ---------------------------------------------------------------------------
__global__ __launch_bounds__(256) void gemm_kernel(
    const float* __restrict__ X, const float* __restrict__ W,
    const float* __restrict__ bias, float* __restrict__ out,
    float scale, int split)
{
    __shared__ float As[16][68];   // [kk][m]
    __shared__ float Bs[16][68];   // [kk][n]
    const int tid = threadIdx.x;
    const int tx = tid & 15, ty = tid >> 4;
    const int bm = blockIdx.y * 64, bn = blockIdx.x * 64;

    const int arow = tid >> 2, akq = tid & 3;     // A fill: 64 rows x 4 float4 chunks of k
    const int bkk  = tid >> 4, bnq = tid & 15;    // B fill: 16 k rows x 16 float4 chunks of n

    float acc[4][4] = {};

    for (int k0 = 0; k0 < 512; k0 += 16) {
        float4 xv = *(const float4*)(X + (bm + arow) * 512 + k0 + akq * 4);
        float4 wv = *(const float4*)(W + (k0 + bkk) * 512 + bn + bnq * 4);
        As[akq*4+0][arow] = xv.x;
        As[akq*4+1][arow] = xv.y;
        As[akq*4+2][arow] = xv.z;
        As[akq*4+3][arow] = xv.w;
        *(float4*)&Bs[bkk][bnq*4] = wv;
        __syncthreads();
        #pragma unroll
        for (int kk = 0; kk < 16; kk++) {
            float4 av = *(float4*)&As[kk][ty*4];
            float4 bv = *(float4*)&Bs[kk][tx*4];
            float aa[4] = {av.x, av.y, av.z, av.w};
            float bb[4] = {bv.x, bv.y, bv.z, bv.w};
            #pragma unroll
            for (int i = 0; i < 4; i++)
                #pragma unroll
                for (int j = 0; j < 4; j++)
                    acc[i][j] = fmaf(aa[i], bb[j], acc[i][j]);
        }
        __syncthreads();
    }

    float4 bvv = *(const float4*)(bias + bn + tx*4);
    float bb[4] = {bvv.x, bvv.y, bvv.z, bvv.w};
    const int n0 = bn + tx * 4;
    #pragma unroll
    for (int i = 0; i < 4; i++) {
        int row = bm + ty * 4 + i;
        float4 o;
        o.x = (acc[i][0] + bb[0]) * scale;
        o.y = (acc[i][1] + bb[1]) * scale;
        o.z = (acc[i][2] + bb[2]) * scale;
        o.w = (acc[i][3] + bb[3]) * scale;
        if (split) {
            int batch = row >> 11, s = row & 2047;
            int h = n0 >> 6, dh = n0 & 63;
            *(float4*)(out + (((batch * NH + h) * 2048 + s) * 64 + dh)) = o;
        } else {
            *(float4*)(out + row * 512 + n0) = o;
        }
    }
}

// ---------------------------------------------------------------------------
// Flash attention with fused TISA RBF bias.
// Grid: (Q/64, H, B). Block 256 = 16x16, thread owns 4x4 of the 64x64 tile.
// ---------------------------------------------------------------------------
#define ATTN_SMEM_FLOATS (4 * 64 * 68 + 4 * 64)

__global__ __launch_bounds__(256, 2) void attn_kernel(
    const float* __restrict__ qlocs, const float* __restrict__ klocs,
    const float* __restrict__ pa, const float* __restrict__ pb,
    const float* __restrict__ pc, const int* __restrict__ vlens)
{
    extern __shared__ float smem[];
    float* Qs  = smem;                 // [64][68]  (q row, dh)
    float* KsT = Qs  + 64 * 68;        // [64][68]  (dh, key)
    float* Vs  = KsT + 64 * 68;        // [64][68]  (key, dh)
    float* Ps  = Vs  + 64 * 68;        // [64][68]  (q row, key)
    float* qlx = Ps  + 64 * 68;        // [64]
    float* qly = qlx + 64;
    float* klx = qly + 64;
    float* kly = klx + 64;

    const int tid = threadIdx.x;
    const int tx = tid & 15, ty = tid >> 4;
    const int q0 = blockIdx.x * 64;
    const int h  = blockIdx.y;
    const int b  = blockIdx.z;
    const int vlen = vlens[b];

    // head RBF params
    float ah[NF], nb[NF], cc[NF];
    #pragma unroll
    for (int f = 0; f < NF; f++) {
        ah[f] = pa[h * NF + f];
        nb[f] = -fabsf(pb[h * NF + f]) * LOG2E;  // exp(-|b| t^2) = ex2(nb * t^2)
        cc[f] = pc[h * NF + f];
    }

    // Q tile (resident for whole CTA)
    const float* qbase = g_q + ((size_t)(b * NH + h) * NQ + q0) * 64;
    for (int i = tid; i < 1024; i += 256) {
        int r = i >> 4, cq = i & 15;
        *(float4*)&Qs[r * 68 + cq * 4] = *(const float4*)(qbase + r * 64 + cq * 4);
    }
    if (tid < 64) {
        float2 ql = *(const float2*)(qlocs + ((size_t)b * NQ + q0 + tid) * 2);
        qlx[tid] = ql.x; qly[tid] = ql.y;
    }
    __syncthreads();

    float qx[4], qy[4];
    #pragma unroll
    for (int i = 0; i < 4; i++) { qx[i] = qlx[ty*4 + i]; qy[i] = qly[ty*4 + i]; }

    float acc[4][4] = {};
    float m[4], l[4];
    #pragma unroll
    for (int i = 0; i < 4; i++) { m[i] = -CUDART_INF_F; l[i] = 0.f; }

    const int ntiles = (vlen + 63) >> 6;
    const float* kbaseptr = g_k + (size_t)(b * NH + h) * NK * 64;
    const float* vbaseptr = g_v + (size_t)(b * NH + h) * NK * 64;

    for (int t = 0; t < ntiles; t++) {
        const int kb = t * 64;
        __syncthreads();  // prior PV done before overwriting K/V/P

        // K tile (transposed into smem), V tile (natural)
        #pragma unroll
        for (int it = 0; it < 4; it++) {
            int i = tid + it * 256;
            {   // transposed K store: lanes vary key fast -> ~2-way STS conflict only
                int key = (i >> 2) & 63;
                int cq  = (i & 3) | (it << 2);
                float4 kv = *(const float4*)(kbaseptr + (size_t)(kb + key) * 64 + cq * 4);
                KsT[(cq*4+0) * 68 + key] = kv.x;
                KsT[(cq*4+1) * 68 + key] = kv.y;
                KsT[(cq*4+2) * 68 + key] = kv.z;
                KsT[(cq*4+3) * 68 + key] = kv.w;
            }
            {   // V natural: fully coalesced + conflict-free
                int key = i >> 4, cq = i & 15;
                *(float4*)&Vs[key * 68 + cq * 4] =
                    *(const float4*)(vbaseptr + (size_t)(kb + key) * 64 + cq * 4);
            }
        }
        if (tid < 64) {
            float2 kl = *(const float2*)(klocs + ((size_t)b * NK + kb + tid) * 2);
            klx[tid] = kl.x; kly[tid] = kl.y;
        }
        __syncthreads();

        // ---- scores: S = Q @ K^T ----
        float s[4][4] = {};
        #pragma unroll
        for (int d4 = 0; d4 < 64; d4 += 4) {
            float aq[4][4];
            #pragma unroll
            for (int i = 0; i < 4; i++) {
                float4 av = *(float4*)&Qs[(ty*4 + i) * 68 + d4];
                aq[i][0] = av.x; aq[i][1] = av.y; aq[i][2] = av.z; aq[i][3] = av.w;
            }
            #pragma unroll
            for (int u = 0; u < 4; u++) {
                float4 kvv = *(float4*)&KsT[(d4 + u) * 68 + tx * 4];
                float kr[4] = {kvv.x, kvv.y, kvv.z, kvv.w};
                #pragma unroll
                for (int i = 0; i < 4; i++)
                    #pragma unroll
                    for (int j = 0; j < 4; j++)
                        s[i][j] = fmaf(aq[i][u], kr[j], s[i][j]);
            }
        }

        // ---- TISA RBF bias ----
        float kx[4], ky[4];
        #pragma unroll
        for (int j = 0; j < 4; j++) { kx[j] = klx[tx*4 + j]; ky[j] = kly[tx*4 + j]; }
        #pragma unroll
        for (int i = 0; i < 4; i++) {
            #pragma unroll
            for (int j = 0; j < 4; j++) {
                float dx = qx[i] - kx[j], dy = qy[i] - ky[j];
                float d2 = fmaf(dx, dx, dy * dy);
                d2 = fmaxf(d2, 1e-20f);
                float dist = d2 * rsqrtaf(d2);
                float bias = 0.f;
                #pragma unroll
                for (int f = 0; f < NF; f++) {
                    float tt = dist - cc[f];
                    bias = fmaf(ah[f], ex2f(nb[f] * tt * tt), bias);
                }
                s[i][j] += bias;
            }
        }

        // ---- valid_lens mask (only last tile can be partial) ----
        if (kb + 64 > vlen) {
            #pragma unroll
            for (int j = 0; j < 4; j++) {
                if (kb + tx * 4 + j >= vlen) {
                    #pragma unroll
                    for (int i = 0; i < 4; i++) s[i][j] = -CUDART_INF_F;
                }
            }
        }

        // ---- online softmax (row groups are 16 lanes within each half-warp) ----
        #pragma unroll
        for (int i = 0; i < 4; i++) {
            float tm = fmaxf(fmaxf(s[i][0], s[i][1]), fmaxf(s[i][2], s[i][3]));
            #pragma unroll
            for (int off = 1; off < 16; off <<= 1)
                tm = fmaxf(tm, __shfl_xor_sync(0xffffffffu, tm, off));
            float mn = fmaxf(m[i], tm);
            float sc = ex2f((m[i] - mn) * LOG2E);
            m[i] = mn;
            float rs = 0.f;
            #pragma unroll
            for (int j = 0; j < 4; j++) {
                float p = ex2f((s[i][j] - mn) * LOG2E);
                s[i][j] = p;
                rs += p;
            }
            #pragma unroll
            for (int off = 1; off < 16; off <<= 1)
                rs += __shfl_xor_sync(0xffffffffu, rs, off);
            l[i] = l[i] * sc + rs;
            #pragma unroll
            for (int j = 0; j < 4; j++) acc[i][j] *= sc;
        }

        // ---- write P, then PV ----
        #pragma unroll
        for (int i = 0; i < 4; i++) {
            float4 pv = {s[i][0], s[i][1], s[i][2], s[i][3]};
            *(float4*)&Ps[(ty*4 + i) * 68 + tx * 4] = pv;
        }
        __syncthreads();

        #pragma unroll
        for (int k4 = 0; k4 < 64; k4 += 4) {
            float pq[4][4];
            #pragma unroll
            for (int i = 0; i < 4; i++) {
                float4 p4 = *(float4*)&Ps[(ty*4 + i) * 68 + k4];
                pq[i][0] = p4.x; pq[i][1] = p4.y; pq[i][2] = p4.z; pq[i][3] = p4.w;
            }
            #pragma unroll
            for (int u = 0; u < 4; u++) {
                float4 vv = *(float4*)&Vs[(k4 + u) * 68 + tx * 4];
                float vr[4] = {vv.x, vv.y, vv.z, vv.w};
                #pragma unroll
                for (int i = 0; i < 4; i++)
                    #pragma unroll
                    for (int j = 0; j < 4; j++)
                        acc[i][j] = fmaf(pq[i][u], vr[j], acc[i][j]);
            }
        }
    }

    // ---- normalize + write context ----
    #pragma unroll
    for (int i = 0; i < 4; i++) {
        float linv = 1.0f / l[i];
        int qrow = q0 + ty * 4 + i;
        float4 o = {acc[i][0] * linv, acc[i][1] * linv,
                    acc[i][2] * linv, acc[i][3] * linv};
        *(float4*)(g_ctx + ((size_t)(b * NQ + qrow)) * 512 + h * 64 + tx * 4) = o;
    }
}

// ---------------------------------------------------------------------------
extern "C" void kernel_launch(void* const* d_in, const int* in_sizes, int n_in,
                              void* d_out, int out_size)
{
    const float* qs    = (const float*)d_in[0];
    const float* ks    = (const float*)d_in[1];
    const float* vs    = (const float*)d_in[2];
    const float* qlocs = (const float*)d_in[3];
    const float* klocs = (const float*)d_in[4];
    const float* Wq    = (const float*)d_in[5];
    const float* bq    = (const float*)d_in[6];
    const float* Wk    = (const float*)d_in[7];
    const float* bk    = (const float*)d_in[8];
    const float* Wv    = (const float*)d_in[9];
    const float* bv    = (const float*)d_in[10];
    const float* Wo    = (const float*)d_in[11];
    const float* bo    = (const float*)d_in[12];
    const float* pa    = (const float*)d_in[13];
    const float* pb    = (const float*)d_in[14];
    const float* pc    = (const float*)d_in[15];
    const int*   vlens = (const int*)d_in[16];
    float* out = (float*)d_out;

    float *gq, *gk, *gv, *gctx;
    cudaGetSymbolAddress((void**)&gq,   g_q);
    cudaGetSymbolAddress((void**)&gk,   g_k);
    cudaGetSymbolAddress((void**)&gv,   g_v);
    cudaGetSymbolAddress((void**)&gctx, g_ctx);

    const size_t attn_smem = ATTN_SMEM_FLOATS * sizeof(float);  // 70656 B
    cudaFuncSetAttribute(attn_kernel,
                         cudaFuncAttributeMaxDynamicSharedMemorySize,
                         (int)attn_smem);

    dim3 ggrid(8, 64);   // N tiles x M tiles for M=4096, N=512
    gemm_kernel<<<ggrid, 256>>>(qs, Wq, bq, gq, 0.125f, 1);  // 1/sqrt(64)
    gemm_kernel<<<ggrid, 256>>>(ks, Wk, bk, gk, 1.0f, 1);
    gemm_kernel<<<ggrid, 256>>>(vs, Wv, bv, gv, 1.0f, 1);

    attn_kernel<<<dim3(NQ / 64, NH, NB), 256, attn_smem>>>(
        qlocs, klocs, pa, pb, pc, vlens);

    gemm_kernel<<<ggrid, 256>>>(gctx, Wo, bo, out, 1.0f, 0);
}

// round 6
// speedup vs baseline: 1.7057x; 1.7057x over previous
#include <cuda_runtime.h>
#include <math_constants.h>
#include <cstdint>

#define NB 2
#define NQ 2048
#define NKK 2048
#define DMODEL 512
#define NH 8
#define DHEAD 64
#define NF 5
#define LOG2E 1.44269504088896f

#define NLUT 2048
#define DMAX 14.143f
#define LUT_H (DMAX / NLUT)
#define LUT_K (NLUT / DMAX)

// Scratch (allocation-free rule: __device__ globals)
__device__ float g_q[NB*NH*NQ*DHEAD];     // [b][h][q][dh]
__device__ float g_k[NB*NH*NKK*DHEAD];    // [b][h][k][dh]
__device__ float g_v[NB*NH*NKK*DHEAD];    // [b][h][k][dh]
__device__ float g_ctx[NB*NQ*DMODEL];     // [b][q][h*64+dh]

__device__ __forceinline__ float ex2f(float x) {
    float y; asm("ex2.approx.ftz.f32 %0, %1;" : "=f"(y) : "f"(x)); return y;
}
__device__ __forceinline__ float rsqrtaf(float x) {
    float y; asm("rsqrt.approx.ftz.f32 %0, %1;" : "=f"(y) : "f"(x)); return y;
}
__device__ __forceinline__ uint32_t f2tf32(float x) {
    uint32_t r; asm("cvt.rna.tf32.f32 %0, %1;" : "=r"(r) : "f"(x)); return r;
}
__device__ __forceinline__ void mma_tf32(float c[4],
    uint32_t a0, uint32_t a1, uint32_t a2, uint32_t a3,
    uint32_t b0, uint32_t b1)
{
    asm volatile(
        "mma.sync.aligned.m16n8k8.row.col.f32.tf32.tf32.f32 "
        "{%0,%1,%2,%3}, {%4,%5,%6,%7}, {%8,%9}, {%0,%1,%2,%3};\n"
        : "+f"(c[0]), "+f"(c[1]), "+f"(c[2]), "+f"(c[3])
        : "r"(a0), "r"(a1), "r"(a2), "r"(a3), "r"(b0), "r"(b1));
}

// ---------------------------------------------------------------------------
// tf32 GEMM: out = (X[M,512] @ W[512,512] + bias) * scale
// CTA 64x64 tile, 128 threads (4 warps), warp = 16 rows x 64 cols.
// split==1: out[((batch*NH+h)*2048 + s)*64 + dh]; split==0: out[row*512+n].
// ---------------------------------------------------------------------------
__global__ __launch_bounds__(128) void gemm_tf32_kernel(
    const float* __restrict__ X, const float* __restrict__ W,
    const float* __restrict__ bias, float* __restrict__ out,
    float scale, int split)
{
    __shared__ float As[64 * 20];   // [m][k16] pad 20
    __shared__ float Bs[16 * 72];   // [k][n64] pad 72

    const int tid  = threadIdx.x;
    const int warp = tid >> 5, lane = tid & 31;
    const int grp  = lane >> 2, qd = lane & 3;
    const int bm = blockIdx.y * 64, bn = blockIdx.x * 64;

    float C[8][4] = {};

    for (int k0 = 0; k0 < 512; k0 += 16) {
        __syncthreads();
        #pragma unroll
        for (int i = tid; i < 256; i += 128) {          // A: 64x16
            int m = i >> 2, c = i & 3;
            float4 x = *(const float4*)(X + (size_t)(bm + m) * 512 + k0 + c * 4);
            uint4 t = { f2tf32(x.x), f2tf32(x.y), f2tf32(x.z), f2tf32(x.w) };
            *(uint4*)&As[m * 20 + c * 4] = t;
        }
        #pragma unroll
        for (int i = tid; i < 256; i += 128) {          // B: 16x64
            int kk = i >> 4, c = i & 15;
            float4 w = *(const float4*)(W + (size_t)(k0 + kk) * 512 + bn + c * 4);
            uint4 t = { f2tf32(w.x), f2tf32(w.y), f2tf32(w.z), f2tf32(w.w) };
            *(uint4*)&Bs[kk * 72 + c * 4] = t;
        }
        __syncthreads();

        #pragma unroll
        for (int k8 = 0; k8 < 2; k8++) {
            int kc = k8 * 8 + qd;
            uint32_t a0 = __float_as_uint(As[(warp*16 + grp    ) * 20 + kc    ]);
            uint32_t a1 = __float_as_uint(As[(warp*16 + grp + 8) * 20 + kc    ]);
            uint32_t a2 = __float_as_uint(As[(warp*16 + grp    ) * 20 + kc + 4]);
            uint32_t a3 = __float_as_uint(As[(warp*16 + grp + 8) * 20 + kc + 4]);
            #pragma unroll
            for (int j = 0; j < 8; j++) {
                uint32_t b0 = __float_as_uint(Bs[(k8*8 + qd    ) * 72 + j*8 + grp]);
                uint32_t b1 = __float_as_uint(Bs[(k8*8 + qd + 4) * 72 + j*8 + grp]);
                mma_tf32(C[j], a0, a1, a2, a3, b0, b1);
            }
        }
    }

    const int r0 = bm + warp * 16 + grp;
    #pragma unroll
    for (int j = 0; j < 8; j++) {
        int n = bn + j * 8 + 2 * qd;
        float b0 = bias[n], b1 = bias[n + 1];
        float2 o0 = { (C[j][0] + b0) * scale, (C[j][1] + b1) * scale };
        float2 o1 = { (C[j][2] + b0) * scale, (C[j][3] + b1) * scale };
        if (split) {
            int h = n >> 6, dh = n & 63;
            int ba = r0 >> 11, s0 = r0 & 2047;
            *(float2*)(out + (((size_t)(ba * NH + h) * NQ + s0) * 64 + dh)) = o0;
            int r1 = r0 + 8, ba1 = r1 >> 11, s1 = r1 & 2047;
            *(float2*)(out + (((size_t)(ba1 * NH + h) * NQ + s1) * 64 + dh)) = o1;
        } else {
            *(float2*)(out + (size_t)r0 * 512 + n) = o0;
            *(float2*)(out + (size_t)(r0 + 8) * 512 + n) = o1;
        }
    }
}

// ---------------------------------------------------------------------------
// Flash attention, tf32 tensor cores + TISA bias via per-head LUT.
// Grid (Q/64, H, B), 128 threads (4 warps), warp = 16 q-rows x 64 keys.
// ---------------------------------------------------------------------------
#define ATTN_SMEM_BYTES ((64*68*3 + 64*72) * 4 + NLUT * 8 + 4 * 64 * 4)

__global__ __launch_bounds__(128) void attn_kernel(
    const float* __restrict__ qlocs, const float* __restrict__ klocs,
    const float* __restrict__ pa, const float* __restrict__ pb,
    const float* __restrict__ pc, const int* __restrict__ vlens)
{
    extern __shared__ float smem[];
    float*  Qs   = smem;                  // [64][68] tf32 bits
    float*  Ks   = Qs + 64 * 68;          // [64][68]
    float*  Vs   = Ks + 64 * 68;          // [64][72]
    float*  Ps   = Vs + 64 * 72;          // [64][68]
    float2* lut  = (float2*)(Ps + 64 * 68);   // [2048] (value, slope)
    float*  qlx  = (float*)(lut + NLUT);
    float*  qly  = qlx + 64;
    float*  klx  = qly + 64;
    float*  kly  = klx + 64;

    const int tid  = threadIdx.x;
    const int warp = tid >> 5, lane = tid & 31;
    const int grp  = lane >> 2, qd = lane & 3;
    const int q0 = blockIdx.x * 64;
    const int h  = blockIdx.y;
    const int b  = blockIdx.z;
    const int vlen = vlens[b];

    // ---- build per-head bias LUT ----
    float ah[NF], nbf[NF], cf[NF];
    #pragma unroll
    for (int f = 0; f < NF; f++) {
        ah[f]  = pa[h * NF + f];
        nbf[f] = -fabsf(pb[h * NF + f]) * LOG2E;
        cf[f]  = pc[h * NF + f];
    }
    for (int i = tid; i < NLUT; i += 128) {
        float d0 = i * LUT_H, d1 = d0 + LUT_H;
        float v0 = 0.f, v1 = 0.f;
        #pragma unroll
        for (int f = 0; f < NF; f++) {
            float t0 = d0 - cf[f], t1 = d1 - cf[f];
            v0 = fmaf(ah[f], ex2f(nbf[f] * t0 * t0), v0);
            v1 = fmaf(ah[f], ex2f(nbf[f] * t1 * t1), v1);
        }
        lut[i] = make_float2(v0, (v1 - v0) * (1.0f / LUT_H));
    }

    // ---- Q tile (tf32) + q locs ----
    const float* qbase = g_q + ((size_t)(b * NH + h) * NQ + q0) * 64;
    for (int i = tid; i < 1024; i += 128) {
        int r = i >> 4, c = i & 15;
        float4 qv = *(const float4*)(qbase + (size_t)r * 64 + c * 4);
        uint4 t = { f2tf32(qv.x), f2tf32(qv.y), f2tf32(qv.z), f2tf32(qv.w) };
        *(uint4*)&Qs[r * 68 + c * 4] = t;
    }
    if (tid < 64) {
        float2 ql = *(const float2*)(qlocs + ((size_t)b * NQ + q0 + tid) * 2);
        qlx[tid] = ql.x; qly[tid] = ql.y;
    }
    __syncthreads();

    const int rr = warp * 16 + grp;       // first owned row in tile
    const float qx0 = qlx[rr],     qy0 = qly[rr];
    const float qx1 = qlx[rr + 8], qy1 = qly[rr + 8];

    float O[8][4] = {};
    float m0 = -CUDART_INF_F, m1 = -CUDART_INF_F, l0 = 0.f, l1 = 0.f;

    const int ntiles = (vlen + 63) >> 6;
    const float* kptr = g_k + (size_t)(b * NH + h) * NKK * 64;
    const float* vptr = g_v + (size_t)(b * NH + h) * NKK * 64;

    for (int t = 0; t < ntiles; t++) {
        const int kb = t * 64;
        __syncthreads();
        for (int i = tid; i < 1024; i += 128) {
            int key = i >> 4, c = i & 15;
            float4 kv = *(const float4*)(kptr + (size_t)(kb + key) * 64 + c * 4);
            uint4 kt = { f2tf32(kv.x), f2tf32(kv.y), f2tf32(kv.z), f2tf32(kv.w) };
            *(uint4*)&Ks[key * 68 + c * 4] = kt;
            float4 vv = *(const float4*)(vptr + (size_t)(kb + key) * 64 + c * 4);
            uint4 vt = { f2tf32(vv.x), f2tf32(vv.y), f2tf32(vv.z), f2tf32(vv.w) };
            *(uint4*)&Vs[key * 72 + c * 4] = vt;
        }
        if (tid < 64) {
            float2 kl = *(const float2*)(klocs + ((size_t)b * NKK + kb + tid) * 2);
            klx[tid] = kl.x; kly[tid] = kl.y;
        }
        __syncthreads();

        // ---- scores: S = Q @ K^T via tf32 mma ----
        float S[8][4] = {};
        #pragma unroll
        for (int k8 = 0; k8 < 8; k8++) {
            int kc = k8 * 8 + qd;
            uint32_t a0 = __float_as_uint(Qs[(rr    ) * 68 + kc    ]);
            uint32_t a1 = __float_as_uint(Qs[(rr + 8) * 68 + kc    ]);
            uint32_t a2 = __float_as_uint(Qs[(rr    ) * 68 + kc + 4]);
            uint32_t a3 = __float_as_uint(Qs[(rr + 8) * 68 + kc + 4]);
            #pragma unroll
            for (int j = 0; j < 8; j++) {
                uint32_t b0 = __float_as_uint(Ks[(j*8 + grp) * 68 + kc    ]);
                uint32_t b1 = __float_as_uint(Ks[(j*8 + grp) * 68 + kc + 4]);
                mma_tf32(S[j], a0, a1, a2, a3, b0, b1);
            }
        }

        // ---- bias (LUT) + mask ----
        const bool partial = (kb + 64 > vlen);
        #pragma unroll
        for (int j = 0; j < 8; j++) {
            int cl = j * 8 + 2 * qd;
            #pragma unroll
            for (int e = 0; e < 2; e++) {
                float kx = klx[cl + e], ky = kly[cl + e];
                // row rr
                float dx = qx0 - kx, dy = qy0 - ky;
                float d2 = fmaf(dx, dx, dy * dy);
                d2 = fmaxf(d2, 1e-24f);
                float d = d2 * rsqrtaf(d2);
                int ii = (int)(d * LUT_K); ii = min(ii, NLUT - 1);
                float2 vs = lut[ii];
                S[j][e] += fmaf(vs.y, d - ii * LUT_H, vs.x);
                // row rr+8
                dx = qx1 - kx; dy = qy1 - ky;
                d2 = fmaf(dx, dx, dy * dy);
                d2 = fmaxf(d2, 1e-24f);
                d = d2 * rsqrtaf(d2);
                ii = (int)(d * LUT_K); ii = min(ii, NLUT - 1);
                vs = lut[ii];
                S[j][2 + e] += fmaf(vs.y, d - ii * LUT_H, vs.x);
            }
            if (partial) {
                if (kb + cl     >= vlen) { S[j][0] = -CUDART_INF_F; S[j][2] = -CUDART_INF_F; }
                if (kb + cl + 1 >= vlen) { S[j][1] = -CUDART_INF_F; S[j][3] = -CUDART_INF_F; }
            }
        }

        // ---- online softmax (rows rr, rr+8; quad lanes share rows) ----
        float tm0 = -CUDART_INF_F, tm1 = -CUDART_INF_F;
        #pragma unroll
        for (int j = 0; j < 8; j++) {
            tm0 = fmaxf(tm0, fmaxf(S[j][0], S[j][1]));
            tm1 = fmaxf(tm1, fmaxf(S[j][2], S[j][3]));
        }
        tm0 = fmaxf(tm0, __shfl_xor_sync(0xffffffffu, tm0, 1));
        tm0 = fmaxf(tm0, __shfl_xor_sync(0xffffffffu, tm0, 2));
        tm1 = fmaxf(tm1, __shfl_xor_sync(0xffffffffu, tm1, 1));
        tm1 = fmaxf(tm1, __shfl_xor_sync(0xffffffffu, tm1, 2));
        float mn0 = fmaxf(m0, tm0), mn1 = fmaxf(m1, tm1);
        float sc0 = ex2f((m0 - mn0) * LOG2E);
        float sc1 = ex2f((m1 - mn1) * LOG2E);
        m0 = mn0; m1 = mn1;

        float rs0 = 0.f, rs1 = 0.f;
        #pragma unroll
        for (int j = 0; j < 8; j++) {
            int cl = j * 8 + 2 * qd;
            uint32_t p0 = f2tf32(ex2f((S[j][0] - mn0) * LOG2E));
            uint32_t p1 = f2tf32(ex2f((S[j][1] - mn1 + (mn1 - mn1)) * LOG2E));  // placeholder fixed below
            // NOTE: S[j][1] belongs to row rr -> use mn0
            p1 = f2tf32(ex2f((S[j][1] - mn0) * LOG2E));
            uint32_t p2 = f2tf32(ex2f((S[j][2] - mn1) * LOG2E));
            uint32_t p3 = f2tf32(ex2f((S[j][3] - mn1) * LOG2E));
            rs0 += __uint_as_float(p0) + __uint_as_float(p1);
            rs1 += __uint_as_float(p2) + __uint_as_float(p3);
            float2 w0 = { __uint_as_float(p0), __uint_as_float(p1) };
            float2 w1 = { __uint_as_float(p2), __uint_as_float(p3) };
            *(float2*)&Ps[(rr    ) * 68 + cl] = w0;
            *(float2*)&Ps[(rr + 8) * 68 + cl] = w1;
        }
        rs0 += __shfl_xor_sync(0xffffffffu, rs0, 1);
        rs0 += __shfl_xor_sync(0xffffffffu, rs0, 2);
        rs1 += __shfl_xor_sync(0xffffffffu, rs1, 1);
        rs1 += __shfl_xor_sync(0xffffffffu, rs1, 2);
        l0 = l0 * sc0 + rs0;
        l1 = l1 * sc1 + rs1;
        #pragma unroll
        for (int j = 0; j < 8; j++) {
            O[j][0] *= sc0; O[j][1] *= sc0;
            O[j][2] *= sc1; O[j][3] *= sc1;
        }
        __syncwarp();   // Ps region is per-warp private

        // ---- PV: O += P @ V via tf32 mma ----
        #pragma unroll
        for (int k8 = 0; k8 < 8; k8++) {
            int kc = k8 * 8 + qd;
            uint32_t a0 = __float_as_uint(Ps[(rr    ) * 68 + kc    ]);
            uint32_t a1 = __float_as_uint(Ps[(rr + 8) * 68 + kc    ]);
            uint32_t a2 = __float_as_uint(Ps[(rr    ) * 68 + kc + 4]);
            uint32_t a3 = __float_as_uint(Ps[(rr + 8) * 68 + kc + 4]);
            #pragma unroll
            for (int j = 0; j < 8; j++) {
                uint32_t b0 = __float_as_uint(Vs[(k8*8 + qd    ) * 72 + j*8 + grp]);
                uint32_t b1 = __float_as_uint(Vs[(k8*8 + qd + 4) * 72 + j*8 + grp]);
                mma_tf32(O[j], a0, a1, a2, a3, b0, b1);
            }
        }
    }

    // ---- normalize + write context ----
    float li0 = 1.0f / l0, li1 = 1.0f / l1;
    float* obase = g_ctx + ((size_t)(b * NQ + q0 + rr)) * 512 + h * 64;
    #pragma unroll
    for (int j = 0; j < 8; j++) {
        int cl = j * 8 + 2 * qd;
        float2 o0 = { O[j][0] * li0, O[j][1] * li0 };
        float2 o1 = { O[j][2] * li1, O[j][3] * li1 };
        *(float2*)(obase + cl) = o0;
        *(float2*)(obase + (size_t)8 * 512 + cl) = o1;
    }
}

// ---------------------------------------------------------------------------
extern "C" void kernel_launch(void* const* d_in, const int* in_sizes, int n_in,
                              void* d_out, int out_size)
{
    const float* qs    = (const float*)d_in[0];
    const float* ks    = (const float*)d_in[1];
    const float* vs    = (const float*)d_in[2];
    const float* qlocs = (const float*)d_in[3];
    const float* klocs = (const float*)d_in[4];
    const float* Wq    = (const float*)d_in[5];
    const float* bq    = (const float*)d_in[6];
    const float* Wk    = (const float*)d_in[7];
    const float* bk    = (const float*)d_in[8];
    const float* Wv    = (const float*)d_in[9];
    const float* bv    = (const float*)d_in[10];
    const float* Wo    = (const float*)d_in[11];
    const float* bo    = (const float*)d_in[12];
    const float* pa    = (const float*)d_in[13];
    const float* pb    = (const float*)d_in[14];
    const float* pc    = (const float*)d_in[15];
    const int*   vlens = (const int*)d_in[16];
    float* out = (float*)d_out;

    float *gq, *gk, *gv, *gctx;
    cudaGetSymbolAddress((void**)&gq,   g_q);
    cudaGetSymbolAddress((void**)&gk,   g_k);
    cudaGetSymbolAddress((void**)&gv,   g_v);
    cudaGetSymbolAddress((void**)&gctx, g_ctx);

    cudaFuncSetAttribute(attn_kernel,
                         cudaFuncAttributeMaxDynamicSharedMemorySize,
                         ATTN_SMEM_BYTES);

    dim3 ggrid(8, 64);   // N/64, M/64 for M=4096, N=512
    gemm_tf32_kernel<<<ggrid, 128>>>(qs, Wq, bq, gq, 0.125f, 1);  // 1/sqrt(64)
    gemm_tf32_kernel<<<ggrid, 128>>>(ks, Wk, bk, gk, 1.0f, 1);
    gemm_tf32_kernel<<<ggrid, 128>>>(vs, Wv, bv, gv, 1.0f, 1);

    attn_kernel<<<dim3(NQ / 64, NH, NB), 128, ATTN_SMEM_BYTES>>>(
        qlocs, klocs, pa, pb, pc, vlens);

    gemm_tf32_kernel<<<ggrid, 128>>>(gctx, Wo, bo, out, 1.0f, 0);
}

// round 9
// speedup vs baseline: 2.3917x; 1.4022x over previous
#include <cuda_runtime.h>
#include <math_constants.h>
#include <cstdint>

#define NB 2
#define NQ 2048
#define NKK 2048
#define DMODEL 512
#define NH 8
#define DHEAD 64
#define NF 5
#define LOG2E 1.44269504088896f

#define NLUT 2048
#define DMAX 14.143f
#define LUT_H (DMAX / NLUT)
#define LUT_K (NLUT / DMAX)

// Scratch (allocation-free rule: __device__ globals)
__device__ float g_q[NB*NH*NQ*DHEAD];     // [b][h][q][dh]
__device__ float g_k[NB*NH*NKK*DHEAD];    // [b][h][k][dh]
__device__ float g_v[NB*NH*NKK*DHEAD];    // [b][h][k][dh]
__device__ float g_ctx[NB*NQ*DMODEL];     // [b][q][h*64+dh]

__device__ __forceinline__ float ex2f(float x) {
    float y; asm("ex2.approx.ftz.f32 %0, %1;" : "=f"(y) : "f"(x)); return y;
}
__device__ __forceinline__ float rsqrtaf(float x) {
    float y; asm("rsqrt.approx.ftz.f32 %0, %1;" : "=f"(y) : "f"(x)); return y;
}
__device__ __forceinline__ uint32_t f2tf32(float x) {
    uint32_t r; asm("cvt.rna.tf32.f32 %0, %1;" : "=r"(r) : "f"(x)); return r;
}
__device__ __forceinline__ void mma_tf32(float c[4],
    uint32_t a0, uint32_t a1, uint32_t a2, uint32_t a3,
    uint32_t b0, uint32_t b1)
{
    asm volatile(
        "mma.sync.aligned.m16n8k8.row.col.f32.tf32.tf32.f32 "
        "{%0,%1,%2,%3}, {%4,%5,%6,%7}, {%8,%9}, {%0,%1,%2,%3};\n"
        : "+f"(c[0]), "+f"(c[1]), "+f"(c[2]), "+f"(c[3])
        : "r"(a0), "r"(a1), "r"(a2), "r"(a3), "r"(b0), "r"(b1));
}

// ---------------------------------------------------------------------------
// tf32 GEMM: out = (X[M,512] @ W[512,512] + bias) * scale
// CTA 128x64 tile, 256 threads (8 warps), warp = 16 rows x 64 cols.
// split==1: out[((batch*NH+h)*2048 + s)*64 + dh]; split==0: out[row*512+n].
// ---------------------------------------------------------------------------
__global__ __launch_bounds__(256) void gemm_tf32_kernel(
    const float* __restrict__ X, const float* __restrict__ W,
    const float* __restrict__ bias, float* __restrict__ out,
    float scale, int split)
{
    __shared__ float As[128 * 20];  // [m][k16] pad 20
    __shared__ float Bs[16 * 72];   // [k][n64] pad 72

    const int tid  = threadIdx.x;
    const int warp = tid >> 5, lane = tid & 31;
    const int grp  = lane >> 2, qd = lane & 3;
    const int bm = blockIdx.y * 128, bn = blockIdx.x * 64;

    float C[8][4] = {};

    for (int k0 = 0; k0 < 512; k0 += 16) {
        __syncthreads();
        #pragma unroll
        for (int i = tid; i < 512; i += 256) {          // A: 128x16
            int m = i >> 2, c = i & 3;
            float4 x = *(const float4*)(X + (size_t)(bm + m) * 512 + k0 + c * 4);
            uint4 t = { f2tf32(x.x), f2tf32(x.y), f2tf32(x.z), f2tf32(x.w) };
            *(uint4*)&As[m * 20 + c * 4] = t;
        }
        {                                                // B: 16x64
            int kk = tid >> 4, c = tid & 15;
            float4 w = *(const float4*)(W + (size_t)(k0 + kk) * 512 + bn + c * 4);
            uint4 t = { f2tf32(w.x), f2tf32(w.y), f2tf32(w.z), f2tf32(w.w) };
            *(uint4*)&Bs[kk * 72 + c * 4] = t;
        }
        __syncthreads();

        #pragma unroll
        for (int k8 = 0; k8 < 2; k8++) {
            int kc = k8 * 8 + qd;
            uint32_t a0 = __float_as_uint(As[(warp*16 + grp    ) * 20 + kc    ]);
            uint32_t a1 = __float_as_uint(As[(warp*16 + grp + 8) * 20 + kc    ]);
            uint32_t a2 = __float_as_uint(As[(warp*16 + grp    ) * 20 + kc + 4]);
            uint32_t a3 = __float_as_uint(As[(warp*16 + grp + 8) * 20 + kc + 4]);
            #pragma unroll
            for (int j = 0; j < 8; j++) {
                uint32_t b0 = __float_as_uint(Bs[(k8*8 + qd    ) * 72 + j*8 + grp]);
                uint32_t b1 = __float_as_uint(Bs[(k8*8 + qd + 4) * 72 + j*8 + grp]);
                mma_tf32(C[j], a0, a1, a2, a3, b0, b1);
            }
        }
    }

    const int r0 = bm + warp * 16 + grp;
    #pragma unroll
    for (int j = 0; j < 8; j++) {
        int n = bn + j * 8 + 2 * qd;
        float b0 = bias[n], b1 = bias[n + 1];
        float2 o0 = { (C[j][0] + b0) * scale, (C[j][1] + b1) * scale };
        float2 o1 = { (C[j][2] + b0) * scale, (C[j][3] + b1) * scale };
        if (split) {
            int h = n >> 6, dh = n & 63;
            int ba = r0 >> 11, s0 = r0 & 2047;
            *(float2*)(out + (((size_t)(ba * NH + h) * NQ + s0) * 64 + dh)) = o0;
            int r1 = r0 + 8, ba1 = r1 >> 11, s1 = r1 & 2047;
            *(float2*)(out + (((size_t)(ba1 * NH + h) * NQ + s1) * 64 + dh)) = o1;
        } else {
            *(float2*)(out + (size_t)r0 * 512 + n) = o0;
            *(float2*)(out + (size_t)(r0 + 8) * 512 + n) = o1;
        }
    }
}

// ---------------------------------------------------------------------------
// Flash attention, tf32 tensor cores + TISA bias via per-head LUT.
// Grid (Q/128, H, B) = 256 CTAs (one wave at 2 CTAs/SM).
// 256 threads (8 warps), warp = 16 q-rows x 64 keys.
// P relayout accumulator->A-fragment done with intra-quad shuffles (no smem).
// ---------------------------------------------------------------------------
#define ATTN_SMEM_FLOATS (128*68 + 64*68 + 64*72 + NLUT*2 + 2*128 + 2*64)
#define ATTN_SMEM_BYTES  (ATTN_SMEM_FLOATS * 4)

__global__ __launch_bounds__(256, 2) void attn_kernel(
    const float* __restrict__ qlocs, const float* __restrict__ klocs,
    const float* __restrict__ pa, const float* __restrict__ pb,
    const float* __restrict__ pc, const int* __restrict__ vlens)
{
    extern __shared__ float smem[];
    float*  Qs   = smem;                      // [128][68] tf32 bits
    float*  Ks   = Qs + 128 * 68;             // [64][68]
    float*  Vs   = Ks + 64 * 68;              // [64][72]
    float2* lut  = (float2*)(Vs + 64 * 72);   // [2048] (value, slope)
    float*  qlx  = (float*)(lut + NLUT);      // [128]
    float*  qly  = qlx + 128;
    float*  klx  = qly + 128;                 // [64]
    float*  kly  = klx + 64;

    const int tid  = threadIdx.x;
    const int warp = tid >> 5, lane = tid & 31;
    const int grp  = lane >> 2, qd = lane & 3;
    const int q0 = blockIdx.x * 128;
    const int h  = blockIdx.y;
    const int b  = blockIdx.z;
    const int vlen = vlens[b];

    // ---- build per-head bias LUT ----
    float ah[NF], nbf[NF], cf[NF];
    #pragma unroll
    for (int f = 0; f < NF; f++) {
        ah[f]  = pa[h * NF + f];
        nbf[f] = -fabsf(pb[h * NF + f]) * LOG2E;
        cf[f]  = pc[h * NF + f];
    }
    for (int i = tid; i < NLUT; i += 256) {
        float d0 = i * LUT_H, d1 = d0 + LUT_H;
        float v0 = 0.f, v1 = 0.f;
        #pragma unroll
        for (int f = 0; f < NF; f++) {
            float t0 = d0 - cf[f], t1 = d1 - cf[f];
            v0 = fmaf(ah[f], ex2f(nbf[f] * t0 * t0), v0);
            v1 = fmaf(ah[f], ex2f(nbf[f] * t1 * t1), v1);
        }
        lut[i] = make_float2(v0, (v1 - v0) * (1.0f / LUT_H));
    }

    // ---- Q tile (tf32) + q locs ----
    const float* qbase = g_q + ((size_t)(b * NH + h) * NQ + q0) * 64;
    for (int i = tid; i < 2048; i += 256) {
        int r = i >> 4, c = i & 15;
        float4 qv = *(const float4*)(qbase + (size_t)r * 64 + c * 4);
        uint4 t = { f2tf32(qv.x), f2tf32(qv.y), f2tf32(qv.z), f2tf32(qv.w) };
        *(uint4*)&Qs[r * 68 + c * 4] = t;
    }
    if (tid < 128) {
        float2 ql = *(const float2*)(qlocs + ((size_t)b * NQ + q0 + tid) * 2);
        qlx[tid] = ql.x; qly[tid] = ql.y;
    }
    __syncthreads();

    const int rr = warp * 16 + grp;       // first owned q-row in CTA tile
    const float qx0 = qlx[rr],     qy0 = qly[rr];
    const float qx1 = qlx[rr + 8], qy1 = qly[rr + 8];

    float O[8][4] = {};
    float m0 = -CUDART_INF_F, m1 = -CUDART_INF_F, l0 = 0.f, l1 = 0.f;

    const int ntiles = (vlen + 63) >> 6;
    const float* kptr = g_k + (size_t)(b * NH + h) * NKK * 64;
    const float* vptr = g_v + (size_t)(b * NH + h) * NKK * 64;

    for (int t = 0; t < ntiles; t++) {
        const int kb = t * 64;
        __syncthreads();   // prior PV (reads Vs) done before refill
        for (int i = tid; i < 1024; i += 256) {
            int key = i >> 4, c = i & 15;
            float4 kv = *(const float4*)(kptr + (size_t)(kb + key) * 64 + c * 4);
            uint4 kt = { f2tf32(kv.x), f2tf32(kv.y), f2tf32(kv.z), f2tf32(kv.w) };
            *(uint4*)&Ks[key * 68 + c * 4] = kt;
            float4 vv = *(const float4*)(vptr + (size_t)(kb + key) * 64 + c * 4);
            uint4 vt = { f2tf32(vv.x), f2tf32(vv.y), f2tf32(vv.z), f2tf32(vv.w) };
            *(uint4*)&Vs[key * 72 + c * 4] = vt;
        }
        if (tid < 64) {
            float2 kl = *(const float2*)(klocs + ((size_t)b * NKK + kb + tid) * 2);
            klx[tid] = kl.x; kly[tid] = kl.y;
        }
        __syncthreads();

        // ---- scores: S = Q @ K^T via tf32 mma ----
        float S[8][4] = {};
        #pragma unroll
        for (int k8 = 0; k8 < 8; k8++) {
            int kc = k8 * 8 + qd;
            uint32_t a0 = __float_as_uint(Qs[(rr    ) * 68 + kc    ]);
            uint32_t a1 = __float_as_uint(Qs[(rr + 8) * 68 + kc    ]);
            uint32_t a2 = __float_as_uint(Qs[(rr    ) * 68 + kc + 4]);
            uint32_t a3 = __float_as_uint(Qs[(rr + 8) * 68 + kc + 4]);
            #pragma unroll
            for (int j = 0; j < 8; j++) {
                uint32_t b0 = __float_as_uint(Ks[(j*8 + grp) * 68 + kc    ]);
                uint32_t b1 = __float_as_uint(Ks[(j*8 + grp) * 68 + kc + 4]);
                mma_tf32(S[j], a0, a1, a2, a3, b0, b1);
            }
        }

        // ---- bias (LUT) + mask ----
        const bool partial = (kb + 64 > vlen);
        #pragma unroll
        for (int j = 0; j < 8; j++) {
            int cl = j * 8 + 2 * qd;
            #pragma unroll
            for (int e = 0; e < 2; e++) {
                float kx = klx[cl + e], ky = kly[cl + e];
                // row rr
                float dx = qx0 - kx, dy = qy0 - ky;
                float d2 = fmaf(dx, dx, dy * dy);
                d2 = fmaxf(d2, 1e-24f);
                float d = d2 * rsqrtaf(d2);
                int ii = (int)(d * LUT_K); ii = min(ii, NLUT - 1);
                float2 vs = lut[ii];
                S[j][e] += fmaf(vs.y, d - ii * LUT_H, vs.x);
                // row rr+8
                dx = qx1 - kx; dy = qy1 - ky;
                d2 = fmaf(dx, dx, dy * dy);
                d2 = fmaxf(d2, 1e-24f);
                d = d2 * rsqrtaf(d2);
                ii = (int)(d * LUT_K); ii = min(ii, NLUT - 1);
                vs = lut[ii];
                S[j][2 + e] += fmaf(vs.y, d - ii * LUT_H, vs.x);
            }
            if (partial) {
                if (kb + cl     >= vlen) { S[j][0] = -CUDART_INF_F; S[j][2] = -CUDART_INF_F; }
                if (kb + cl + 1 >= vlen) { S[j][1] = -CUDART_INF_F; S[j][3] = -CUDART_INF_F; }
            }
        }

        // ---- online softmax (rows rr, rr+8; quad lanes share rows) ----
        float tm0 = -CUDART_INF_F, tm1 = -CUDART_INF_F;
        #pragma unroll
        for (int j = 0; j < 8; j++) {
            tm0 = fmaxf(tm0, fmaxf(S[j][0], S[j][1]));
            tm1 = fmaxf(tm1, fmaxf(S[j][2], S[j][3]));
        }
        tm0 = fmaxf(tm0, __shfl_xor_sync(0xffffffffu, tm0, 1));
        tm0 = fmaxf(tm0, __shfl_xor_sync(0xffffffffu, tm0, 2));
        tm1 = fmaxf(tm1, __shfl_xor_sync(0xffffffffu, tm1, 1));
        tm1 = fmaxf(tm1, __shfl_xor_sync(0xffffffffu, tm1, 2));
        float mn0 = fmaxf(m0, tm0), mn1 = fmaxf(m1, tm1);
        float sc0 = ex2f((m0 - mn0) * LOG2E);
        float sc1 = ex2f((m1 - mn1) * LOG2E);
        m0 = mn0; m1 = mn1;

        // ---- exp + accumulator->A-fragment relayout via intra-quad shuffles
        // S (C-layout) cols {2qd, 2qd+1}; A fragment needs cols {qd, qd+4}.
        // col c of an 8-block lives in quad lane c>>1, element c&1.
        float rs0 = 0.f, rs1 = 0.f;
        const int s1 = qd >> 1, s2 = s1 + 2;
        const bool odd = (qd & 1);
        #pragma unroll
        for (int j = 0; j < 8; j++) {
            float p0 = ex2f((S[j][0] - mn0) * LOG2E);
            float p1 = ex2f((S[j][1] - mn0) * LOG2E);
            float p2 = ex2f((S[j][2] - mn1) * LOG2E);
            float p3 = ex2f((S[j][3] - mn1) * LOG2E);
            rs0 += p0 + p1;
            rs1 += p2 + p3;
            float u0 = __shfl_sync(0xffffffffu, p0, s1, 4);
            float u1 = __shfl_sync(0xffffffffu, p1, s1, 4);
            float w0 = __shfl_sync(0xffffffffu, p0, s2, 4);
            float w1 = __shfl_sync(0xffffffffu, p1, s2, 4);
            float t0 = __shfl_sync(0xffffffffu, p2, s1, 4);
            float t1 = __shfl_sync(0xffffffffu, p3, s1, 4);
            float v0 = __shfl_sync(0xffffffffu, p2, s2, 4);
            float v1 = __shfl_sync(0xffffffffu, p3, s2, 4);
            // reuse S as fragment storage (bit-cast tf32)
            S[j][0] = __uint_as_float(f2tf32(odd ? u1 : u0));  // a0: row lo, col qd
            S[j][1] = __uint_as_float(f2tf32(odd ? t1 : t0));  // a1: row hi, col qd
            S[j][2] = __uint_as_float(f2tf32(odd ? w1 : w0));  // a2: row lo, col qd+4
            S[j][3] = __uint_as_float(f2tf32(odd ? v1 : v0));  // a3: row hi, col qd+4
        }
        rs0 += __shfl_xor_sync(0xffffffffu, rs0, 1);
        rs0 += __shfl_xor_sync(0xffffffffu, rs0, 2);
        rs1 += __shfl_xor_sync(0xffffffffu, rs1, 1);
        rs1 += __shfl_xor_sync(0xffffffffu, rs1, 2);
        l0 = l0 * sc0 + rs0;
        l1 = l1 * sc1 + rs1;
        #pragma unroll
        for (int j = 0; j < 8; j++) {
            O[j][0] *= sc0; O[j][1] *= sc0;
            O[j][2] *= sc1; O[j][3] *= sc1;
        }

        // ---- PV: O += P @ V via tf32 mma (A fragments in registers) ----
        #pragma unroll
        for (int k8 = 0; k8 < 8; k8++) {
            uint32_t a0 = __float_as_uint(S[k8][0]);
            uint32_t a1 = __float_as_uint(S[k8][1]);
            uint32_t a2 = __float_as_uint(S[k8][2]);
            uint32_t a3 = __float_as_uint(S[k8][3]);
            #pragma unroll
            for (int j = 0; j < 8; j++) {
                uint32_t b0 = __float_as_uint(Vs[(k8*8 + qd    ) * 72 + j*8 + grp]);
                uint32_t b1 = __float_as_uint(Vs[(k8*8 + qd + 4) * 72 + j*8 + grp]);
                mma_tf32(O[j], a0, a1, a2, a3, b0, b1);
            }
        }
    }

    // ---- normalize + write context ----
    float li0 = 1.0f / l0, li1 = 1.0f / l1;
    float* obase = g_ctx + ((size_t)(b * NQ + q0 + rr)) * 512 + h * 64;
    #pragma unroll
    for (int j = 0; j < 8; j++) {
        int cl = j * 8 + 2 * qd;
        float2 o0 = { O[j][0] * li0, O[j][1] * li0 };
        float2 o1 = { O[j][2] * li1, O[j][3] * li1 };
        *(float2*)(obase + cl) = o0;
        *(float2*)(obase + (size_t)8 * 512 + cl) = o1;
    }
}

// ---------------------------------------------------------------------------
extern "C" void kernel_launch(void* const* d_in, const int* in_sizes, int n_in,
                              void* d_out, int out_size)
{
    const float* qs    = (const float*)d_in[0];
    const float* ks    = (const float*)d_in[1];
    const float* vs    = (const float*)d_in[2];
    const float* qlocs = (const float*)d_in[3];
    const float* klocs = (const float*)d_in[4];
    const float* Wq    = (const float*)d_in[5];
    const float* bq    = (const float*)d_in[6];
    const float* Wk    = (const float*)d_in[7];
    const float* bk    = (const float*)d_in[8];
    const float* Wv    = (const float*)d_in[9];
    const float* bv    = (const float*)d_in[10];
    const float* Wo    = (const float*)d_in[11];
    const float* bo    = (const float*)d_in[12];
    const float* pa    = (const float*)d_in[13];
    const float* pb    = (const float*)d_in[14];
    const float* pc    = (const float*)d_in[15];
    const int*   vlens = (const int*)d_in[16];
    float* out = (float*)d_out;

    float *gq, *gk, *gv, *gctx;
    cudaGetSymbolAddress((void**)&gq,   g_q);
    cudaGetSymbolAddress((void**)&gk,   g_k);
    cudaGetSymbolAddress((void**)&gv,   g_v);
    cudaGetSymbolAddress((void**)&gctx, g_ctx);

    cudaFuncSetAttribute(attn_kernel,
                         cudaFuncAttributeMaxDynamicSharedMemorySize,
                         ATTN_SMEM_BYTES);

    dim3 ggrid(8, 32);   // N/64, M/128 for M=4096, N=512
    gemm_tf32_kernel<<<ggrid, 256>>>(qs, Wq, bq, gq, 0.125f, 1);  // 1/sqrt(64)
    gemm_tf32_kernel<<<ggrid, 256>>>(ks, Wk, bk, gk, 1.0f, 1);
    gemm_tf32_kernel<<<ggrid, 256>>>(vs, Wv, bv, gv, 1.0f, 1);

    attn_kernel<<<dim3(NQ / 128, NH, NB), 256, ATTN_SMEM_BYTES>>>(
        qlocs, klocs, pa, pb, pc, vlens);

    gemm_tf32_kernel<<<ggrid, 256>>>(gctx, Wo, bo, out, 1.0f, 0);
}